// round 8
// baseline (speedup 1.0000x reference)
#include <cuda_runtime.h>
#include <cstdint>

// B=4096, T=1024, H=15
// Inputs: x[B*T], w_ih[15], w_hh[225], b_ih[15], b_hh[15], w_lin[15], b_lin[1]
// Output: out[B*T] float32
//
// 16-lane group, TWO batches (A,B) per thread. Lane i<15 owns hidden row i for
// both batches; lane 15 is the linear head (one step delayed) for both.
// h exchange: interleaved {A_j,B_j} pairs in smem -> 8x LDS.128 delivers both
// batches' h; 1x STS.64 + 1 WARPSYNC per pair-step. Two independent FMA/tanh
// chains per thread hide each other's latency.

#define T_      1024
#define THREADS 128           // 4 warps = 8 groups = 16 batches per CTA
#define GROUPS  8
#define BPC     16
#define GRID    (4096 / BPC)  // 256 CTAs
#define GSTRIDE 40            // floats per group buffer: 160B (16B-aligned, bank-spread)

__device__ __forceinline__ float tanha(float x) {
    float r; asm("tanh.approx.f32 %0, %1;" : "=f"(r) : "f"(x)); return r;
}

__global__ void __launch_bounds__(THREADS)
rnn_kernel(const float* __restrict__ x,
           const float* __restrict__ w_ih, const float* __restrict__ w_hh,
           const float* __restrict__ b_ih, const float* __restrict__ b_hh,
           const float* __restrict__ w_lin, const float* __restrict__ b_lin,
           float* __restrict__ out)
{
    __shared__ __align__(16) float hbuf[2][GROUPS][GSTRIDE];   // 2.5KB

    const int tid  = threadIdx.x;
    const int lane = tid & 31;
    const int li   = lane & 15;
    const int g    = tid >> 4;               // 0..7: group within CTA
    const int bA   = blockIdx.x * BPC + 2 * g;
    const bool is_head = (li == 15);

    // Per-lane weights (row li; lane 15 = head row)
    float w[15], wih, bias;
    if (!is_head) {
#pragma unroll
        for (int j = 0; j < 15; j++) w[j] = w_hh[li * 15 + j];
        wih  = w_ih[li];
        bias = b_ih[li] + b_hh[li];
    } else {
#pragma unroll
        for (int j = 0; j < 15; j++) w[j] = w_lin[j];
        wih  = 0.0f;
        bias = b_lin[0];
    }

    // h0 = 0 for both batches
    *reinterpret_cast<float2*>(&hbuf[0][g][2 * li]) = make_float2(0.f, 0.f);
    __syncwarp();

    const float* xrowA = x   + (size_t)bA * T_;
    const float* xrowB = xrowA + T_;
    float*       orowA = out + (size_t)bA * T_;
    float*       orowB = orowA + T_;
    float* const hb0 = &hbuf[0][g][0];
    float* const hb1 = &hbuf[1][g][0];

    float oA0=0.f, oA1=0.f, oA2=0.f, oA3=0.f;
    float oB0=0.f, oB1=0.f, oB2=0.f, oB3=0.f;

    float4 xnA = *reinterpret_cast<const float4*>(xrowA);   // x_A[0..3]
    float4 xnB = *reinterpret_cast<const float4*>(xrowB);   // x_B[0..3]

#pragma unroll 1
    for (int m = 0; m < 256; ++m) {
        const float4 xcA = xnA;
        const float4 xcB = xnB;
        const int mn = ((m + 1) & 255) << 2;
        xnA = *reinterpret_cast<const float4*>(xrowA + mn);
        xnB = *reinterpret_cast<const float4*>(xrowB + mn);

#pragma unroll
        for (int u = 0; u < 4; ++u) {
            const float* hr = (u & 1) ? hb1 : hb0;
            float*       hw = (u & 1) ? hb0 : hb1;
            const float xvA = (u == 0) ? xcA.x : (u == 1) ? xcA.y : (u == 2) ? xcA.z : xcA.w;
            const float xvB = (u == 0) ? xcB.x : (u == 1) ? xcB.y : (u == 2) ? xcB.z : xcB.w;

            // Broadcast-load both batches' h: 8x LDS.128 of {A_j,B_j,A_j+1,B_j+1}
            float hA[16], hB[16];
#pragma unroll
            for (int j = 0; j < 8; ++j) {
                float4 v = *reinterpret_cast<const float4*>(hr + 4 * j);
                hA[2 * j]     = v.x;  hB[2 * j]     = v.y;
                hA[2 * j + 1] = v.z;  hB[2 * j + 1] = v.w;   // j=7: slots 15 junk
            }

            // Two independent 15-term dots, 3 accumulators each
            float pA = fmaf(xvA, wih, bias);
            float pB = fmaf(xvB, wih, bias);
            float a0 = fmaf(w[0], hA[0], pA);
            float a1 = w[1] * hA[1];
            float a2 = w[2] * hA[2];
            float c0 = fmaf(w[0], hB[0], pB);
            float c1 = w[1] * hB[1];
            float c2 = w[2] * hB[2];
#pragma unroll
            for (int j = 3; j < 15; j += 3) {
                a0 = fmaf(w[j + 0], hA[j + 0], a0);
                a1 = fmaf(w[j + 1], hA[j + 1], a1);
                a2 = fmaf(w[j + 2], hA[j + 2], a2);
                c0 = fmaf(w[j + 0], hB[j + 0], c0);
                c1 = fmaf(w[j + 1], hB[j + 1], c1);
                c2 = fmaf(w[j + 2], hB[j + 2], c2);
            }
            const float accA = a0 + (a1 + a2);
            const float accB = c0 + (c1 + c2);

            // Write new h pair (lane15's slots are junk, never read)
            *reinterpret_cast<float2*>(hw + 2 * li) =
                make_float2(tanha(accA), tanha(accB));

            // Head schedule: lane15's acc at step t=4m+u equals out[t-1]
            if (u == 0) {
                oA3 = accA; oB3 = accB;
                if (m > 0 && is_head) {
                    *reinterpret_cast<float4*>(orowA + ((m - 1) << 2)) =
                        make_float4(oA0, oA1, oA2, oA3);
                    *reinterpret_cast<float4*>(orowB + ((m - 1) << 2)) =
                        make_float4(oB0, oB1, oB2, oB3);
                }
            } else if (u == 1) { oA0 = accA; oB0 = accB; }
            else if (u == 2)   { oA1 = accA; oB1 = accB; }
            else               { oA2 = accA; oB2 = accB; }
            __syncwarp();
        }
    }

    // Epilogue: out[1023] = head dot on final h (in buf0); flush out[1020..1023]
    {
        float hA[16], hB[16];
#pragma unroll
        for (int j = 0; j < 8; ++j) {
            float4 v = *reinterpret_cast<const float4*>(hb0 + 4 * j);
            hA[2 * j]     = v.x;  hB[2 * j]     = v.y;
            hA[2 * j + 1] = v.z;  hB[2 * j + 1] = v.w;
        }
        float a0 = bias, a1 = 0.f, a2 = 0.f;
        float c0 = bias, c1 = 0.f, c2 = 0.f;
#pragma unroll
        for (int j = 0; j < 15; j += 3) {
            a0 = fmaf(w[j + 0], hA[j + 0], a0);
            a1 = fmaf(w[j + 1], hA[j + 1], a1);
            a2 = fmaf(w[j + 2], hA[j + 2], a2);
            c0 = fmaf(w[j + 0], hB[j + 0], c0);
            c1 = fmaf(w[j + 1], hB[j + 1], c1);
            c2 = fmaf(w[j + 2], hB[j + 2], c2);
        }
        oA3 = a0 + (a1 + a2);
        oB3 = c0 + (c1 + c2);
        if (is_head) {
            *reinterpret_cast<float4*>(orowA + (T_ - 4)) = make_float4(oA0, oA1, oA2, oA3);
            *reinterpret_cast<float4*>(orowB + (T_ - 4)) = make_float4(oB0, oB1, oB2, oB3);
        }
    }
}

extern "C" void kernel_launch(void* const* d_in, const int* in_sizes, int n_in,
                              void* d_out, int out_size)
{
    const float* x     = (const float*)d_in[0];
    const float* w_ih  = (const float*)d_in[1];
    const float* w_hh  = (const float*)d_in[2];
    const float* b_ih  = (const float*)d_in[3];
    const float* b_hh  = (const float*)d_in[4];
    const float* w_lin = (const float*)d_in[5];
    const float* b_lin = (const float*)d_in[6];
    float* out = (float*)d_out;
    rnn_kernel<<<GRID, THREADS>>>(x, w_ih, w_hh, b_ih, b_hh, w_lin, b_lin, out);
}

// round 9
// speedup vs baseline: 1.7398x; 1.7398x over previous
#include <cuda_runtime.h>
#include <cstdint>

// B=4096, T=1024, H=15
// Inputs: x[B*T], w_ih[15], w_hh[225], b_ih[15], b_hh[15], w_lin[15], b_lin[1]
// Output: out[B*T] float32
//
// 8 lanes per batch; lane li (0..7) owns hidden rows 2li and 2li+1.
// Lane 7's second row is the linear head (one step delayed).
// Per step: 4x LDS.128 broadcast + two 15-dots (4 accums each) + MUFU.TANH
// + 1x STS.64 + 1 WARPSYNC. Output flushed via predicated STG.128 (no BSSY).

#define T_      1024
#define THREADS 128
#define GROUPS  16            // batches per CTA
#define GRID    (4096 / GROUPS)
#define HSTRIDE 20            // floats per group: 80B, 16B-aligned, LDS.128-conflict-free

__device__ __forceinline__ float tanha(float x) {
    float r; asm("tanh.approx.f32 %0, %1;" : "=f"(r) : "f"(x)); return r;
}

// Predicated 128-bit global store: single @p STG.128, no BSSY/BSYNC.
__device__ __forceinline__ void stg128_pred(float* p, float a, float b, float c, float d, int pred) {
    asm volatile("{\n\t"
        ".reg .pred p0;\n\t"
        "setp.ne.s32 p0, %5, 0;\n\t"
        "@p0 st.global.v4.f32 [%0], {%1, %2, %3, %4};\n\t"
        "}" :: "l"(p), "f"(a), "f"(b), "f"(c), "f"(d), "r"(pred) : "memory");
}

__global__ void __launch_bounds__(THREADS)
rnn_kernel(const float* __restrict__ x,
           const float* __restrict__ w_ih, const float* __restrict__ w_hh,
           const float* __restrict__ b_ih, const float* __restrict__ b_hh,
           const float* __restrict__ w_lin, const float* __restrict__ b_lin,
           float* __restrict__ out)
{
    __shared__ __align__(16) float hbuf[2][GROUPS][HSTRIDE];   // 2.5KB

    const int tid  = threadIdx.x;
    const int lane = tid & 31;
    const int li   = lane & 7;           // lane within group
    const int g    = tid >> 3;           // 0..15: batch within CTA
    const int b0   = blockIdx.x * GROUPS;
    const bool is_head = (li == 7);
    const int  head_i  = is_head ? 1 : 0;

    // Rows 2li and 2li+1. Lane 7: row 14 (regular) + head row (w_lin).
    const int r0 = 2 * li, r1 = 2 * li + 1;
    float w0[15], w1[15], wih0, wih1, bias0, bias1;
#pragma unroll
    for (int j = 0; j < 15; j++) w0[j] = w_hh[r0 * 15 + j];
    wih0  = w_ih[r0];
    bias0 = b_ih[r0] + b_hh[r0];
    if (!is_head) {
#pragma unroll
        for (int j = 0; j < 15; j++) w1[j] = w_hh[r1 * 15 + j];
        wih1  = w_ih[r1];
        bias1 = b_ih[r1] + b_hh[r1];
    } else {
#pragma unroll
        for (int j = 0; j < 15; j++) w1[j] = w_lin[j];
        wih1  = 0.0f;
        bias1 = b_lin[0];
    }

    // h0 = 0
    *reinterpret_cast<float2*>(&hbuf[0][g][2 * li]) = make_float2(0.f, 0.f);
    __syncwarp();

    const float* xrow = x   + (size_t)(b0 + g) * T_;
    float*       orow = out + (size_t)(b0 + g) * T_;
    float* const hb0 = &hbuf[0][g][0];
    float* const hb1 = &hbuf[1][g][0];

    float o0 = 0.f, o1 = 0.f, o2 = 0.f, o3 = 0.f;

    float4 xn = *reinterpret_cast<const float4*>(xrow);   // x[0..3]

#pragma unroll 1
    for (int m = 0; m < 256; ++m) {
        const float4 xc = xn;
        xn = *reinterpret_cast<const float4*>(xrow + (((m + 1) & 255) << 2));
        const int   pstore = head_i & (m > 0 ? 1 : 0);
        float* const paddr = orow + ((m - 1) << 2);

#pragma unroll
        for (int u = 0; u < 4; ++u) {
            const float* hr = (u & 1) ? hb1 : hb0;
            float*       hw = (u & 1) ? hb0 : hb1;
            const float xv = (u == 0) ? xc.x : (u == 1) ? xc.y : (u == 2) ? xc.z : xc.w;

            // Broadcast-load h: 4x LDS.128 (slot 15 junk, never used)
            float h[16];
            {
                float4 v0 = *reinterpret_cast<const float4*>(hr + 0);
                float4 v1 = *reinterpret_cast<const float4*>(hr + 4);
                float4 v2 = *reinterpret_cast<const float4*>(hr + 8);
                float4 v3 = *reinterpret_cast<const float4*>(hr + 12);
                h[0]=v0.x; h[1]=v0.y; h[2]=v0.z; h[3]=v0.w;
                h[4]=v1.x; h[5]=v1.y; h[6]=v1.z; h[7]=v1.w;
                h[8]=v2.x; h[9]=v2.y; h[10]=v2.z; h[11]=v2.w;
                h[12]=v3.x; h[13]=v3.y; h[14]=v3.z; h[15]=v3.w;
            }

            // Two 15-term dots, 4 accumulators each (depth 4 + 2 adds)
            float a0 = fmaf(xv, wih0, bias0);
            float c0 = fmaf(xv, wih1, bias1);
            float a1 = w0[1] * h[1];
            float a2 = w0[2] * h[2];
            float a3 = w0[3] * h[3];
            float c1 = w1[1] * h[1];
            float c2 = w1[2] * h[2];
            float c3 = w1[3] * h[3];
            a0 = fmaf(w0[0], h[0], a0);
            c0 = fmaf(w1[0], h[0], c0);
#pragma unroll
            for (int j = 4; j < 12; j += 4) {
                a0 = fmaf(w0[j + 0], h[j + 0], a0);
                a1 = fmaf(w0[j + 1], h[j + 1], a1);
                a2 = fmaf(w0[j + 2], h[j + 2], a2);
                a3 = fmaf(w0[j + 3], h[j + 3], a3);
                c0 = fmaf(w1[j + 0], h[j + 0], c0);
                c1 = fmaf(w1[j + 1], h[j + 1], c1);
                c2 = fmaf(w1[j + 2], h[j + 2], c2);
                c3 = fmaf(w1[j + 3], h[j + 3], c3);
            }
            a0 = fmaf(w0[12], h[12], a0);
            a1 = fmaf(w0[13], h[13], a1);
            a2 = fmaf(w0[14], h[14], a2);
            c0 = fmaf(w1[12], h[12], c0);
            c1 = fmaf(w1[13], h[13], c1);
            c2 = fmaf(w1[14], h[14], c2);
            const float acc0 = (a0 + a1) + (a2 + a3);
            const float acc1 = (c0 + c1) + (c2 + c3);

            float t0 = tanha(acc0);
            float s1 = tanha(acc1);
            if (is_head) s1 = acc1;            // SEL, no branch
            *reinterpret_cast<float2*>(hw + 2 * li) = make_float2(t0, s1);

            // Head schedule: lane7's acc1 at step t=4m+u equals out[t-1]
            if (u == 0) {
                o3 = acc1;
                stg128_pred(paddr, o0, o1, o2, o3, pstore);
            } else if (u == 1) { o0 = acc1; }
            else if (u == 2)   { o1 = acc1; }
            else               { o2 = acc1; }
            __syncwarp();
        }
    }

    // Epilogue: out[1023] from final h (in hb0), flush out[1020..1023]
    {
        float c0 = bias1, c1 = 0.f, c2 = 0.f, c3 = 0.f;
#pragma unroll
        for (int j = 0; j < 12; j += 4) {
            c0 = fmaf(w1[j + 0], hb0[j + 0], c0);
            c1 = fmaf(w1[j + 1], hb0[j + 1], c1);
            c2 = fmaf(w1[j + 2], hb0[j + 2], c2);
            c3 = fmaf(w1[j + 3], hb0[j + 3], c3);
        }
        c0 = fmaf(w1[12], hb0[12], c0);
        c1 = fmaf(w1[13], hb0[13], c1);
        c2 = fmaf(w1[14], hb0[14], c2);
        o3 = (c0 + c1) + (c2 + c3);
        stg128_pred(orow + (T_ - 4), o0, o1, o2, o3, head_i);
    }
}

extern "C" void kernel_launch(void* const* d_in, const int* in_sizes, int n_in,
                              void* d_out, int out_size)
{
    const float* x     = (const float*)d_in[0];
    const float* w_ih  = (const float*)d_in[1];
    const float* w_hh  = (const float*)d_in[2];
    const float* b_ih  = (const float*)d_in[3];
    const float* b_hh  = (const float*)d_in[4];
    const float* w_lin = (const float*)d_in[5];
    const float* b_lin = (const float*)d_in[6];
    float* out = (float*)d_out;
    rnn_kernel<<<GRID, THREADS>>>(x, w_ih, w_hh, b_ih, b_hh, w_lin, b_lin, out);
}

// round 10
// speedup vs baseline: 1.7847x; 1.0258x over previous
#include <cuda_runtime.h>
#include <cstdint>

// B=4096, T=1024, H=15
// Inputs: x[B*T], w_ih[15], w_hh[225], b_ih[15], b_hh[15], w_lin[15], b_lin[1]
// Output: out[B*T] float32
//
// 8 lanes per batch; lane li (0..7) owns hidden rows 2li and 2li+1; lane 7's
// second row is the linear head (one step delayed).
// Inner loop is fully branchless and has NO warp sync: the warp never
// diverges, so the per-warp in-order smem pipeline orders STS -> LDS.
// Smem ops are asm volatile (memory clobber) to pin program order.

#define T_      1024
#define THREADS 128
#define GROUPS  16            // batches per CTA
#define GRID    (4096 / GROUPS)
#define HSTRIDE 20            // floats per group: 80B, 16B-aligned, conflict-free

__device__ __forceinline__ float tanha(float x) {
    float r; asm("tanh.approx.f32 %0, %1;" : "=f"(r) : "f"(x)); return r;
}
__device__ __forceinline__ float4 lds128(unsigned a) {
    float4 v;
    asm volatile("ld.shared.v4.f32 {%0,%1,%2,%3}, [%4];"
                 : "=f"(v.x), "=f"(v.y), "=f"(v.z), "=f"(v.w) : "r"(a) : "memory");
    return v;
}
__device__ __forceinline__ void sts64(unsigned a, float x, float y) {
    asm volatile("st.shared.v2.f32 [%0], {%1,%2};" :: "r"(a), "f"(x), "f"(y) : "memory");
}
// Predicated 128-bit global store: single @p STG.128, no BSSY/BSYNC.
__device__ __forceinline__ void stg128_pred(float* p, float a, float b, float c, float d, int pred) {
    asm volatile("{\n\t"
        ".reg .pred p0;\n\t"
        "setp.ne.s32 p0, %5, 0;\n\t"
        "@p0 st.global.v4.f32 [%0], {%1, %2, %3, %4};\n\t"
        "}" :: "l"(p), "f"(a), "f"(b), "f"(c), "f"(d), "r"(pred) : "memory");
}

__global__ void __launch_bounds__(THREADS)
rnn_kernel(const float* __restrict__ x,
           const float* __restrict__ w_ih, const float* __restrict__ w_hh,
           const float* __restrict__ b_ih, const float* __restrict__ b_hh,
           const float* __restrict__ w_lin, const float* __restrict__ b_lin,
           float* __restrict__ out)
{
    __shared__ __align__(16) float hbuf[2][GROUPS][HSTRIDE];   // 2.5KB

    const int tid  = threadIdx.x;
    const int lane = tid & 31;
    const int li   = lane & 7;           // lane within group
    const int g    = tid >> 3;           // 0..15: batch within CTA
    const int b0   = blockIdx.x * GROUPS;
    const bool is_head = (li == 7);
    const int  head_i  = is_head ? 1 : 0;

    // Rows 2li and 2li+1. Lane 7: row 14 (regular) + head row (w_lin).
    const int r0 = 2 * li, r1 = 2 * li + 1;
    float w0[15], w1[15], wih0, wih1, bias0, bias1;
#pragma unroll
    for (int j = 0; j < 15; j++) w0[j] = w_hh[r0 * 15 + j];
    wih0  = w_ih[r0];
    bias0 = b_ih[r0] + b_hh[r0];
    if (!is_head) {
#pragma unroll
        for (int j = 0; j < 15; j++) w1[j] = w_hh[r1 * 15 + j];
        wih1  = w_ih[r1];
        bias1 = b_ih[r1] + b_hh[r1];
    } else {
#pragma unroll
        for (int j = 0; j < 15; j++) w1[j] = w_lin[j];
        wih1  = 0.0f;
        bias1 = b_lin[0];
    }

    const unsigned hb0_a = (unsigned)__cvta_generic_to_shared(&hbuf[0][g][0]);
    const unsigned hb1_a = (unsigned)__cvta_generic_to_shared(&hbuf[1][g][0]);
    const unsigned st0_a = hb0_a + 8u * (unsigned)li;   // float2 slot
    const unsigned st1_a = hb1_a + 8u * (unsigned)li;

    // h0 = 0
    sts64(st0_a, 0.f, 0.f);
    __syncwarp();

    const float* xrow = x   + (size_t)(b0 + g) * T_;
    float*       orow = out + (size_t)(b0 + g) * T_;

    float o0 = 0.f, o1 = 0.f, o2 = 0.f, o3 = 0.f;

    float4 xn = *reinterpret_cast<const float4*>(xrow);   // x[0..3]

#pragma unroll 1
    for (int m = 0; m < 256; ++m) {
        const float4 xc = xn;
        xn = *reinterpret_cast<const float4*>(xrow + (((m + 1) & 255) << 2));
        const int    pstore = head_i & (m > 0 ? 1 : 0);
        float* const paddr  = orow + ((m - 1) << 2);

#pragma unroll
        for (int u = 0; u < 4; ++u) {
            const unsigned hr = (u & 1) ? hb1_a : hb0_a;
            const unsigned hw = (u & 1) ? st0_a : st1_a;
            const float xv = (u == 0) ? xc.x : (u == 1) ? xc.y : (u == 2) ? xc.z : xc.w;

            // Broadcast-load h: 4x LDS.128 (slot 15 junk, never used)
            float h[16];
            {
                float4 v0 = lds128(hr);
                float4 v1 = lds128(hr + 16);
                float4 v2 = lds128(hr + 32);
                float4 v3 = lds128(hr + 48);
                h[0]=v0.x; h[1]=v0.y; h[2]=v0.z; h[3]=v0.w;
                h[4]=v1.x; h[5]=v1.y; h[6]=v1.z; h[7]=v1.w;
                h[8]=v2.x; h[9]=v2.y; h[10]=v2.z; h[11]=v2.w;
                h[12]=v3.x; h[13]=v3.y; h[14]=v3.z; h[15]=v3.w;
            }

            // Two 15-term dots (rows r0, r1), 2 accumulators each (R6 tree)
            float xp0 = fmaf(xv, wih0, bias0);
            float xp1 = fmaf(xv, wih1, bias1);
            float a0 = fmaf(w0[0], h[0], xp0);
            float a1 = w0[1] * h[1];
            float c0 = fmaf(w1[0], h[0], xp1);
            float c1 = w1[1] * h[1];
#pragma unroll
            for (int j = 2; j < 14; j += 2) {
                a0 = fmaf(w0[j + 0], h[j + 0], a0);
                a1 = fmaf(w0[j + 1], h[j + 1], a1);
                c0 = fmaf(w1[j + 0], h[j + 0], c0);
                c1 = fmaf(w1[j + 1], h[j + 1], c1);
            }
            a0 = fmaf(w0[14], h[14], a0);
            c0 = fmaf(w1[14], h[14], c0);
            const float acc0 = a0 + a1;
            const float acc1 = c0 + c1;

            float t0 = tanha(acc0);
            float s1 = tanha(acc1);
            if (is_head) s1 = acc1;            // SEL, no divergence
            sts64(hw, t0, s1);

            // Head schedule: lane7's acc1 at step t=4m+u equals out[t-1]
            if (u == 0) {                      // compile-time (unrolled)
                o3 = acc1;
                stg128_pred(paddr, o0, o1, o2, o3, pstore);
            } else if (u == 1) { o0 = acc1; }
            else if (u == 2)   { o1 = acc1; }
            else               { o2 = acc1; }
            // NO warp sync: converged warp + in-order smem pipeline
        }
    }

    __syncwarp();
    // Epilogue: out[1023] from final h (in hbuf[0]), flush out[1020..1023]
    {
        const float* hb0 = &hbuf[0][g][0];
        float c0 = bias1, c1 = 0.f;
#pragma unroll
        for (int j = 0; j < 14; j += 2) {
            c0 = fmaf(w1[j + 0], hb0[j + 0], c0);
            c1 = fmaf(w1[j + 1], hb0[j + 1], c1);
        }
        c0 = fmaf(w1[14], hb0[14], c0);
        o3 = c0 + c1;
        stg128_pred(orow + (T_ - 4), o0, o1, o2, o3, head_i);
    }
}

extern "C" void kernel_launch(void* const* d_in, const int* in_sizes, int n_in,
                              void* d_out, int out_size)
{
    const float* x     = (const float*)d_in[0];
    const float* w_ih  = (const float*)d_in[1];
    const float* w_hh  = (const float*)d_in[2];
    const float* b_ih  = (const float*)d_in[3];
    const float* b_hh  = (const float*)d_in[4];
    const float* w_lin = (const float*)d_in[5];
    const float* b_lin = (const float*)d_in[6];
    float* out = (float*)d_out;
    rnn_kernel<<<GRID, THREADS>>>(x, w_ih, w_hh, b_ih, b_hh, w_lin, b_lin, out);
}